// round 10
// baseline (speedup 1.0000x reference)
#include <cuda_runtime.h>
#include <cuda_bf16.h>

// EigVals_54872502174209 — per-voxel symmetric 3x3 eigenvalues, ascending.
// x = (2, 9, 64, 192, 192) f32 -> out = (4718592, 3) f32.
//
// Pure-streaming DRAM-bound kernel: 170 MB read + 56.6 MB write compulsory,
// zero reuse. Converged config after 9 falsification rounds (cache policy,
// occupancy both directions, VPT, 256-bit vectors, cp.async pipeline,
// persistent grid, block size): VPT=4, BLOCK=256, plain LDG.128/STG.128,
// one-shot grid. Sits at ~6.05 TB/s, the achievable ceiling for this
// 3:1 read:write 10-stream mix (~75% DRAM SOL).
#define NPB 2359296                // voxels per batch = 64*192*192
#define NB  2
#define NVOX (NB * NPB)            // 4,718,592
#define VPT 4                      // voxels per thread (float4 path)
#define NTHREADS (NVOX / VPT)      // 1,179,648
#define BLOCK 256

// Closed-form symmetric 3x3 eigenvalues (Smith's trigonometric method).
// Returns ascending e0 <= e1 <= e2 by construction (theta in [0, pi/3]).
__device__ __forceinline__ void eig3(
    float a00, float a01, float a02, float a11, float a12, float a22,
    float& e0, float& e1, float& e2)
{
    float q  = (a00 + a11 + a22) * (1.0f / 3.0f);
    float d0 = a00 - q, d1 = a11 - q, d2 = a22 - q;
    float off = a01 * a01 + a02 * a02 + a12 * a12;
    float p2  = d0 * d0 + d1 * d1 + d2 * d2 + 2.0f * off;
    p2 = fmaxf(p2, 1e-30f);                 // guard p2==0 (A == q*I)
    float p2s  = p2 * (1.0f / 6.0f);
    float pinv = rsqrtf(p2s);               // MUFU.RSQ
    float p    = p2s * pinv;                // sqrt(p2/6)

    // det(A - q*I) for the symmetrized matrix
    float det = d0 * (d1 * d2 - a12 * a12)
              - a01 * (a01 * d2 - a12 * a02)
              + a02 * (a01 * a12 - d1 * a02);

    float pinv3 = pinv * pinv * pinv;
    float r = 0.5f * det * pinv3;           // det(B)/2, B=(A-qI)/p
    r = fminf(fmaxf(r, -1.0f), 1.0f);

    float theta = acosf(r) * (1.0f / 3.0f); // theta in [0, pi/3]
    float s, c;
    __sincosf(theta, &s, &c);               // MUFU; s >= 0 on this range

    float t3    = 1.7320508075688772f * s;  // sqrt(3)*sin
    float b_hi  = 2.0f * c;                 // largest root of b^3-3b=2r
    float b_lo  = -c - t3;                  // smallest
    float b_mid = -c + t3;                  // middle

    e0 = fmaf(p, b_lo,  q);
    e1 = fmaf(p, b_mid, q);
    e2 = fmaf(p, b_hi,  q);
}

__global__ void __launch_bounds__(BLOCK)
eigvals_kernel(const float* __restrict__ x, float* __restrict__ out)
{
    int t = blockIdx.x * BLOCK + threadIdx.x;      // [0, NTHREADS)
    const int npb4 = NPB / VPT;                    // 589,824
    int b  = (t >= npb4) ? 1 : 0;                  // NB == 2
    int n4 = t - b * npb4;                         // voxel-group within batch

    const float* base = x + (size_t)b * 9 * NPB + (size_t)n4 * VPT;

    // 9 channel planes, each a coalesced float4 load (front-batched: MLP=9)
    float4 v[9];
#pragma unroll
    for (int c = 0; c < 9; ++c)
        v[c] = *reinterpret_cast<const float4*>(base + (size_t)c * NPB);

    float e0[VPT], e1[VPT], e2[VPT];
#pragma unroll
    for (int j = 0; j < VPT; ++j) {
        const float* lane = reinterpret_cast<const float*>(v) + j; // stride 4 per channel
        float m0 = lane[0 * 4], m1 = lane[1 * 4], m2 = lane[2 * 4];
        float m3 = lane[3 * 4], m4 = lane[4 * 4], m5 = lane[5 * 4];
        float m6 = lane[6 * 4], m7 = lane[7 * 4], m8 = lane[8 * 4];
        // symmetrize: channels are row-major 3x3
        float s01 = 0.5f * (m1 + m3);
        float s02 = 0.5f * (m2 + m6);
        float s12 = 0.5f * (m5 + m7);
        eig3(m0, s01, s02, m4, s12, m8, e0[j], e1[j], e2[j]);
    }

    // out layout: (voxel, 3) ascending; base voxel index divisible by 4
    // -> byte offset divisible by 48 -> 16B-aligned; 3x STG.128.
    float* op = out + ((size_t)b * NPB + (size_t)n4 * VPT) * 3;
    float4 o0 = make_float4(e0[0], e1[0], e2[0], e0[1]);
    float4 o1 = make_float4(e1[1], e2[1], e0[2], e1[2]);
    float4 o2 = make_float4(e2[2], e0[3], e1[3], e2[3]);
    reinterpret_cast<float4*>(op)[0] = o0;
    reinterpret_cast<float4*>(op)[1] = o1;
    reinterpret_cast<float4*>(op)[2] = o2;
}

extern "C" void kernel_launch(void* const* d_in, const int* in_sizes, int n_in,
                              void* d_out, int out_size)
{
    const float* x = (const float*)d_in[0];
    float* out = (float*)d_out;
    (void)in_sizes; (void)n_in; (void)out_size;
    eigvals_kernel<<<NTHREADS / BLOCK, BLOCK>>>(x, out);
}

// round 13
// speedup vs baseline: 1.0050x; 1.0050x over previous
#include <cuda_runtime.h>
#include <cuda_bf16.h>

// EigVals_54872502174209 — per-voxel symmetric 3x3 eigenvalues, ascending.
// x = (2, 9, 64, 192, 192) f32 -> out = (4718592, 3) f32.
//
// Converged streaming config (rounds 1-10): VPT=4, BLOCK=256, plain LDG.128,
// one-shot grid, ~6.05 TB/s (~75% DRAM SOL = device ceiling for this 3:1 mix).
// Round-12 isolated probe (round-11 bench was an infra failure): __stcs on
// stores ONLY — evict-first writes preserve L2 capacity for the read streams
// (~26 MB of reads are L2-resident per replay).
#define NPB 2359296                // voxels per batch = 64*192*192
#define NB  2
#define NVOX (NB * NPB)            // 4,718,592
#define VPT 4                      // voxels per thread (float4 path)
#define NTHREADS (NVOX / VPT)      // 1,179,648
#define BLOCK 256

// Closed-form symmetric 3x3 eigenvalues (Smith's trigonometric method).
// Returns ascending e0 <= e1 <= e2 by construction (theta in [0, pi/3]).
__device__ __forceinline__ void eig3(
    float a00, float a01, float a02, float a11, float a12, float a22,
    float& e0, float& e1, float& e2)
{
    float q  = (a00 + a11 + a22) * (1.0f / 3.0f);
    float d0 = a00 - q, d1 = a11 - q, d2 = a22 - q;
    float off = a01 * a01 + a02 * a02 + a12 * a12;
    float p2  = d0 * d0 + d1 * d1 + d2 * d2 + 2.0f * off;
    p2 = fmaxf(p2, 1e-30f);                 // guard p2==0 (A == q*I)
    float p2s  = p2 * (1.0f / 6.0f);
    float pinv = rsqrtf(p2s);               // MUFU.RSQ
    float p    = p2s * pinv;                // sqrt(p2/6)

    // det(A - q*I) for the symmetrized matrix
    float det = d0 * (d1 * d2 - a12 * a12)
              - a01 * (a01 * d2 - a12 * a02)
              + a02 * (a01 * a12 - d1 * a02);

    float pinv3 = pinv * pinv * pinv;
    float r = 0.5f * det * pinv3;           // det(B)/2, B=(A-qI)/p
    r = fminf(fmaxf(r, -1.0f), 1.0f);

    float theta = acosf(r) * (1.0f / 3.0f); // theta in [0, pi/3]
    float s, c;
    __sincosf(theta, &s, &c);               // MUFU; s >= 0 on this range

    float t3    = 1.7320508075688772f * s;  // sqrt(3)*sin
    float b_hi  = 2.0f * c;                 // largest root of b^3-3b=2r
    float b_lo  = -c - t3;                  // smallest
    float b_mid = -c + t3;                  // middle

    e0 = fmaf(p, b_lo,  q);
    e1 = fmaf(p, b_mid, q);
    e2 = fmaf(p, b_hi,  q);
}

__global__ void __launch_bounds__(BLOCK)
eigvals_kernel(const float* __restrict__ x, float* __restrict__ out)
{
    int t = blockIdx.x * BLOCK + threadIdx.x;      // [0, NTHREADS)
    const int npb4 = NPB / VPT;                    // 589,824
    int b  = (t >= npb4) ? 1 : 0;                  // NB == 2
    int n4 = t - b * npb4;                         // voxel-group within batch

    const float* base = x + (size_t)b * 9 * NPB + (size_t)n4 * VPT;

    // 9 channel planes, each a coalesced float4 load (front-batched: MLP=9)
    float4 v[9];
#pragma unroll
    for (int c = 0; c < 9; ++c)
        v[c] = *reinterpret_cast<const float4*>(base + (size_t)c * NPB);

    float e0[VPT], e1[VPT], e2[VPT];
#pragma unroll
    for (int j = 0; j < VPT; ++j) {
        const float* lane = reinterpret_cast<const float*>(v) + j; // stride 4 per channel
        float m0 = lane[0 * 4], m1 = lane[1 * 4], m2 = lane[2 * 4];
        float m3 = lane[3 * 4], m4 = lane[4 * 4], m5 = lane[5 * 4];
        float m6 = lane[6 * 4], m7 = lane[7 * 4], m8 = lane[8 * 4];
        // symmetrize: channels are row-major 3x3
        float s01 = 0.5f * (m1 + m3);
        float s02 = 0.5f * (m2 + m6);
        float s12 = 0.5f * (m5 + m7);
        eig3(m0, s01, s02, m4, s12, m8, e0[j], e1[j], e2[j]);
    }

    // out layout: (voxel, 3) ascending; base voxel index divisible by 4
    // -> byte offset divisible by 48 -> 16B-aligned; 3x STG.128 evict-first.
    float* op = out + ((size_t)b * NPB + (size_t)n4 * VPT) * 3;
    float4 o0 = make_float4(e0[0], e1[0], e2[0], e0[1]);
    float4 o1 = make_float4(e1[1], e2[1], e0[2], e1[2]);
    float4 o2 = make_float4(e2[2], e0[3], e1[3], e2[3]);
    __stcs(reinterpret_cast<float4*>(op) + 0, o0);
    __stcs(reinterpret_cast<float4*>(op) + 1, o1);
    __stcs(reinterpret_cast<float4*>(op) + 2, o2);
}

extern "C" void kernel_launch(void* const* d_in, const int* in_sizes, int n_in,
                              void* d_out, int out_size)
{
    const float* x = (const float*)d_in[0];
    float* out = (float*)d_out;
    (void)in_sizes; (void)n_in; (void)out_size;
    eigvals_kernel<<<NTHREADS / BLOCK, BLOCK>>>(x, out);
}

// round 14
// speedup vs baseline: 1.0537x; 1.0485x over previous
#include <cuda_runtime.h>
#include <cuda_bf16.h>

// EigVals_54872502174209 — per-voxel symmetric 3x3 eigenvalues, ascending.
// x = (2, 9, 64, 192, 192) f32 -> out = (4718592, 3) f32.
//
// Converged streaming config: VPT=4, BLOCK=256, one-shot grid.
// R13 WIN: __stcs stores (evict-first writes) -> 6.12 TB/s, 76.5% SOL.
// R14 probe: __ldlu loads (last-use: each input line is read once then dead;
// discard after delivery frees L1+L2 capacity behind the read cursor).
#define NPB 2359296                // voxels per batch = 64*192*192
#define NB  2
#define NVOX (NB * NPB)            // 4,718,592
#define VPT 4                      // voxels per thread (float4 path)
#define NTHREADS (NVOX / VPT)      // 1,179,648
#define BLOCK 256

// Closed-form symmetric 3x3 eigenvalues (Smith's trigonometric method).
// Returns ascending e0 <= e1 <= e2 by construction (theta in [0, pi/3]).
__device__ __forceinline__ void eig3(
    float a00, float a01, float a02, float a11, float a12, float a22,
    float& e0, float& e1, float& e2)
{
    float q  = (a00 + a11 + a22) * (1.0f / 3.0f);
    float d0 = a00 - q, d1 = a11 - q, d2 = a22 - q;
    float off = a01 * a01 + a02 * a02 + a12 * a12;
    float p2  = d0 * d0 + d1 * d1 + d2 * d2 + 2.0f * off;
    p2 = fmaxf(p2, 1e-30f);                 // guard p2==0 (A == q*I)
    float p2s  = p2 * (1.0f / 6.0f);
    float pinv = rsqrtf(p2s);               // MUFU.RSQ
    float p    = p2s * pinv;                // sqrt(p2/6)

    // det(A - q*I) for the symmetrized matrix
    float det = d0 * (d1 * d2 - a12 * a12)
              - a01 * (a01 * d2 - a12 * a02)
              + a02 * (a01 * a12 - d1 * a02);

    float pinv3 = pinv * pinv * pinv;
    float r = 0.5f * det * pinv3;           // det(B)/2, B=(A-qI)/p
    r = fminf(fmaxf(r, -1.0f), 1.0f);

    float theta = acosf(r) * (1.0f / 3.0f); // theta in [0, pi/3]
    float s, c;
    __sincosf(theta, &s, &c);               // MUFU; s >= 0 on this range

    float t3    = 1.7320508075688772f * s;  // sqrt(3)*sin
    float b_hi  = 2.0f * c;                 // largest root of b^3-3b=2r
    float b_lo  = -c - t3;                  // smallest
    float b_mid = -c + t3;                  // middle

    e0 = fmaf(p, b_lo,  q);
    e1 = fmaf(p, b_mid, q);
    e2 = fmaf(p, b_hi,  q);
}

__global__ void __launch_bounds__(BLOCK)
eigvals_kernel(const float* __restrict__ x, float* __restrict__ out)
{
    int t = blockIdx.x * BLOCK + threadIdx.x;      // [0, NTHREADS)
    const int npb4 = NPB / VPT;                    // 589,824
    int b  = (t >= npb4) ? 1 : 0;                  // NB == 2
    int n4 = t - b * npb4;                         // voxel-group within batch

    const float* base = x + (size_t)b * 9 * NPB + (size_t)n4 * VPT;

    // 9 channel planes, each a coalesced float4 last-use load (MLP=9).
    float4 v[9];
#pragma unroll
    for (int c = 0; c < 9; ++c)
        v[c] = __ldlu(reinterpret_cast<const float4*>(base + (size_t)c * NPB));

    float e0[VPT], e1[VPT], e2[VPT];
#pragma unroll
    for (int j = 0; j < VPT; ++j) {
        const float* lane = reinterpret_cast<const float*>(v) + j; // stride 4 per channel
        float m0 = lane[0 * 4], m1 = lane[1 * 4], m2 = lane[2 * 4];
        float m3 = lane[3 * 4], m4 = lane[4 * 4], m5 = lane[5 * 4];
        float m6 = lane[6 * 4], m7 = lane[7 * 4], m8 = lane[8 * 4];
        // symmetrize: channels are row-major 3x3
        float s01 = 0.5f * (m1 + m3);
        float s02 = 0.5f * (m2 + m6);
        float s12 = 0.5f * (m5 + m7);
        eig3(m0, s01, s02, m4, s12, m8, e0[j], e1[j], e2[j]);
    }

    // out layout: (voxel, 3) ascending; base voxel index divisible by 4
    // -> byte offset divisible by 48 -> 16B-aligned; 3x STG.128 evict-first.
    float* op = out + ((size_t)b * NPB + (size_t)n4 * VPT) * 3;
    float4 o0 = make_float4(e0[0], e1[0], e2[0], e0[1]);
    float4 o1 = make_float4(e1[1], e2[1], e0[2], e1[2]);
    float4 o2 = make_float4(e2[2], e0[3], e1[3], e2[3]);
    __stcs(reinterpret_cast<float4*>(op) + 0, o0);
    __stcs(reinterpret_cast<float4*>(op) + 1, o1);
    __stcs(reinterpret_cast<float4*>(op) + 2, o2);
}

extern "C" void kernel_launch(void* const* d_in, const int* in_sizes, int n_in,
                              void* d_out, int out_size)
{
    const float* x = (const float*)d_in[0];
    float* out = (float*)d_out;
    (void)in_sizes; (void)n_in; (void)out_size;
    eigvals_kernel<<<NTHREADS / BLOCK, BLOCK>>>(x, out);
}

// round 15
// speedup vs baseline: 1.0556x; 1.0017x over previous
#include <cuda_runtime.h>
#include <cuda_bf16.h>

// EigVals_54872502174209 — per-voxel symmetric 3x3 eigenvalues, ascending.
// x = (2, 9, 64, 192, 192) f32 -> out = (4718592, 3) f32.
//
// Converged streaming config: VPT=4, BLOCK=256, one-shot grid.
// R13 WIN: __stcs stores. R14 WIN: __ldlu loads (cross-replay L2 steady-state
// effect, invisible to ncu's flushed-cache capture). dur 38.72 -> 36.93.
// R15 probe: __stwt stores (write-through: no L2 ownership for output lines,
// maximizing L2 capacity for the input stream in the replay steady state).
#define NPB 2359296                // voxels per batch = 64*192*192
#define NB  2
#define NVOX (NB * NPB)            // 4,718,592
#define VPT 4                      // voxels per thread (float4 path)
#define NTHREADS (NVOX / VPT)      // 1,179,648
#define BLOCK 256

// Closed-form symmetric 3x3 eigenvalues (Smith's trigonometric method).
// Returns ascending e0 <= e1 <= e2 by construction (theta in [0, pi/3]).
__device__ __forceinline__ void eig3(
    float a00, float a01, float a02, float a11, float a12, float a22,
    float& e0, float& e1, float& e2)
{
    float q  = (a00 + a11 + a22) * (1.0f / 3.0f);
    float d0 = a00 - q, d1 = a11 - q, d2 = a22 - q;
    float off = a01 * a01 + a02 * a02 + a12 * a12;
    float p2  = d0 * d0 + d1 * d1 + d2 * d2 + 2.0f * off;
    p2 = fmaxf(p2, 1e-30f);                 // guard p2==0 (A == q*I)
    float p2s  = p2 * (1.0f / 6.0f);
    float pinv = rsqrtf(p2s);               // MUFU.RSQ
    float p    = p2s * pinv;                // sqrt(p2/6)

    // det(A - q*I) for the symmetrized matrix
    float det = d0 * (d1 * d2 - a12 * a12)
              - a01 * (a01 * d2 - a12 * a02)
              + a02 * (a01 * a12 - d1 * a02);

    float pinv3 = pinv * pinv * pinv;
    float r = 0.5f * det * pinv3;           // det(B)/2, B=(A-qI)/p
    r = fminf(fmaxf(r, -1.0f), 1.0f);

    float theta = acosf(r) * (1.0f / 3.0f); // theta in [0, pi/3]
    float s, c;
    __sincosf(theta, &s, &c);               // MUFU; s >= 0 on this range

    float t3    = 1.7320508075688772f * s;  // sqrt(3)*sin
    float b_hi  = 2.0f * c;                 // largest root of b^3-3b=2r
    float b_lo  = -c - t3;                  // smallest
    float b_mid = -c + t3;                  // middle

    e0 = fmaf(p, b_lo,  q);
    e1 = fmaf(p, b_mid, q);
    e2 = fmaf(p, b_hi,  q);
}

__global__ void __launch_bounds__(BLOCK)
eigvals_kernel(const float* __restrict__ x, float* __restrict__ out)
{
    int t = blockIdx.x * BLOCK + threadIdx.x;      // [0, NTHREADS)
    const int npb4 = NPB / VPT;                    // 589,824
    int b  = (t >= npb4) ? 1 : 0;                  // NB == 2
    int n4 = t - b * npb4;                         // voxel-group within batch

    const float* base = x + (size_t)b * 9 * NPB + (size_t)n4 * VPT;

    // 9 channel planes, each a coalesced float4 last-use load (MLP=9).
    float4 v[9];
#pragma unroll
    for (int c = 0; c < 9; ++c)
        v[c] = __ldlu(reinterpret_cast<const float4*>(base + (size_t)c * NPB));

    float e0[VPT], e1[VPT], e2[VPT];
#pragma unroll
    for (int j = 0; j < VPT; ++j) {
        const float* lane = reinterpret_cast<const float*>(v) + j; // stride 4 per channel
        float m0 = lane[0 * 4], m1 = lane[1 * 4], m2 = lane[2 * 4];
        float m3 = lane[3 * 4], m4 = lane[4 * 4], m5 = lane[5 * 4];
        float m6 = lane[6 * 4], m7 = lane[7 * 4], m8 = lane[8 * 4];
        // symmetrize: channels are row-major 3x3
        float s01 = 0.5f * (m1 + m3);
        float s02 = 0.5f * (m2 + m6);
        float s12 = 0.5f * (m5 + m7);
        eig3(m0, s01, s02, m4, s12, m8, e0[j], e1[j], e2[j]);
    }

    // out layout: (voxel, 3) ascending; base voxel index divisible by 4
    // -> byte offset divisible by 48 -> 16B-aligned; 3x STG.128 write-through.
    float* op = out + ((size_t)b * NPB + (size_t)n4 * VPT) * 3;
    float4 o0 = make_float4(e0[0], e1[0], e2[0], e0[1]);
    float4 o1 = make_float4(e1[1], e2[1], e0[2], e1[2]);
    float4 o2 = make_float4(e2[2], e0[3], e1[3], e2[3]);
    __stwt(reinterpret_cast<float4*>(op) + 0, o0);
    __stwt(reinterpret_cast<float4*>(op) + 1, o1);
    __stwt(reinterpret_cast<float4*>(op) + 2, o2);
}

extern "C" void kernel_launch(void* const* d_in, const int* in_sizes, int n_in,
                              void* d_out, int out_size)
{
    const float* x = (const float*)d_in[0];
    float* out = (float*)d_out;
    (void)in_sizes; (void)n_in; (void)out_size;
    eigvals_kernel<<<NTHREADS / BLOCK, BLOCK>>>(x, out);
}